// round 2
// baseline (speedup 1.0000x reference)
#include <cuda_runtime.h>
#include <cstdint>

// ---------------------------------------------------------------------------
// TractBundle: 3 masked linears (A: 4096->1024 @64 conn, B: 4096->512 @64,
// C: 2048->512 @32), concat on last dim. B=8, S=1024 -> 8192 tokens.
// Sparse gather-FMA: prep compacts (idx, w*m) per dst row into per-512-slice
// segments (padded to multiple of 4); gather kernel stages x slices in smem
// (stride 513 -> conflict-free random gathers) and accumulates in registers.
// ---------------------------------------------------------------------------

#define NROWS      2048       // 1024 A + 512 B + 512 C
#define ROWCAP     96         // max 64 entries + 8 slices * 3 pad = 88 -> 96
#define SLICE      512
#define XSTR       513        // 513 % 32 == 1 -> bank(lane*513 + idx) = lane+idx
#define NTOK       32
#define TPB        512        // 16 warps
#define SMEM_FLOATS 16896     // max(32*513 = 16416, 16 warps * 32*33 = 16896)

__device__ __align__(16) int   g_idx[NROWS * ROWCAP];   // byte offset within slice
__device__ __align__(16) float g_w  [NROWS * ROWCAP];
__device__ unsigned g_seg[NROWS * 8];                   // start | (padded_count<<16)

// ---------------------------------------------------------------------------
// Prep: one warp per dst row. Ballot-compact nonzero mask positions (ascending,
// so per-slice segments are contiguous), weight = w*m, pad each slice segment
// to a multiple of 4 entries with (0, 0.0f).
// ---------------------------------------------------------------------------
__global__ void prep_kernel(const float* __restrict__ wa, const float* __restrict__ ma,
                            const float* __restrict__ wb, const float* __restrict__ mb,
                            const float* __restrict__ wc, const float* __restrict__ mc)
{
    int gw   = (blockIdx.x * blockDim.x + threadIdx.x) >> 5;
    int lane = threadIdx.x & 31;
    if (gw >= NROWS) return;

    const float *w, *m; int nsl;
    if (gw < 1024)      { w = wa + (size_t)gw * 4096;        m = ma + (size_t)gw * 4096;        nsl = 8; }
    else if (gw < 1536) { w = wb + (size_t)(gw-1024) * 4096; m = mb + (size_t)(gw-1024) * 4096; nsl = 8; }
    else                { w = wc + (size_t)(gw-1536) * 2048; m = mc + (size_t)(gw-1536) * 2048; nsl = 4; }

    int base = gw * ROWCAP;
    int cnt  = 0;
    unsigned ltmask = (1u << lane) - 1u;

    for (int k = 0; k < nsl; k++) {
        int start = cnt;
        for (int c = 0; c < SLICE; c += 32) {
            int   s  = k * SLICE + c + lane;
            float mv = m[s];
            bool  p  = (mv != 0.0f);
            unsigned b = __ballot_sync(0xffffffffu, p);
            if (p) {
                int pos = cnt + __popc(b & ltmask);
                g_idx[base + pos] = (c + lane) * 4;   // byte offset within slice
                g_w  [base + pos] = w[s] * mv;
            }
            cnt += __popc(b);
        }
        int n    = cnt - start;
        int npad = (n + 3) & ~3;
        if (lane < npad - n) {                        // pad with harmless entries
            g_idx[base + cnt + lane] = 0;
            g_w  [base + cnt + lane] = 0.0f;
        }
        cnt = start + npad;
        if (lane == 0) g_seg[gw * 8 + k] = (unsigned)start | ((unsigned)npad << 16);
    }
}

// ---------------------------------------------------------------------------
// Gather kernel. Grid: (256 token tiles, 4 row groups).
//   grp 0: rows    0-511  (x_a)   grp 1: rows  512-1023 (x_a)
//   grp 2: rows 1024-1535 (x_b)   grp 3: rows 1536-2047 (x_c)
// Block: 512 threads / 16 warps; warp w owns 32 rows -> 32 register accs.
// Lane l <-> token t0+l. Per K-slice: cp.async stage -> gather/FMA.
// ---------------------------------------------------------------------------
__device__ __forceinline__ uint32_t smem_u32(const void* p) {
    uint32_t a;
    asm("{ .reg .u64 t; cvta.to.shared.u64 t, %1; cvt.u32.u64 %0, t; }" : "=r"(a) : "l"(p));
    return a;
}

__global__ void __launch_bounds__(TPB, 2)
gather_kernel(const float* __restrict__ xa, const float* __restrict__ xb,
              const float* __restrict__ xc, float* __restrict__ out)
{
    __shared__ float sm[SMEM_FLOATS];

    const int grp = blockIdx.y;
    const int t0  = blockIdx.x * NTOK;

    const float* x; int S, nsl;
    if (grp <= 1)      { x = xa; S = 4096; nsl = 8; }
    else if (grp == 2) { x = xb; S = 4096; nsl = 8; }
    else               { x = xc; S = 2048; nsl = 4; }

    const int tid    = threadIdx.x;
    const int lane   = tid & 31;
    const int warp   = tid >> 5;
    const int myrow0 = grp * 512 + warp * 32;   // global row == output column

    float acc[32];
#pragma unroll
    for (int r = 0; r < 32; r++) acc[r] = 0.0f;

    const uint32_t sm_base  = smem_u32(sm);
    const uint32_t xlane    = sm_base + (uint32_t)(lane * XSTR) * 4u;

    for (int k = 0; k < nsl; k++) {
        if (k) __syncthreads();

        // --- stage slice: 32 tokens x 512 floats, 4B cp.async, conflict-free ---
        const float* xsrc = x + (size_t)t0 * S + k * SLICE;
#pragma unroll
        for (int it = 0; it < (NTOK * SLICE) / TPB; it++) {
            int p  = tid + it * TPB;
            int ti = p >> 9;
            int c  = p & (SLICE - 1);
            uint32_t dst = sm_base + (uint32_t)(ti * XSTR + c) * 4u;
            const float* src = xsrc + (size_t)ti * S + c;
            asm volatile("cp.async.ca.shared.global [%0], [%1], 4;\n"
                         :: "r"(dst), "l"(src) : "memory");
        }
        asm volatile("cp.async.commit_group;\n" ::: "memory");
        asm volatile("cp.async.wait_group 0;\n" ::: "memory");
        __syncthreads();

        // --- gather + FMA over this slice's segment of each of my 32 rows ---
#pragma unroll
        for (int r = 0; r < 32; r++) {
            int row = myrow0 + r;
            unsigned seg = g_seg[row * 8 + k];
            int ebase = row * ROWCAP + (int)(seg & 0xffffu);
            int n     = (int)(seg >> 16);
            const int4*   ip = (const int4*)  (g_idx + ebase);
            const float4* wp = (const float4*)(g_w   + ebase);
            float a = acc[r];
            for (int q = 0; q < n; q += 4) {
                int4   ib = *ip++;
                float4 wv = *wp++;
                float x0, x1, x2, x3;
                asm volatile("ld.shared.f32 %0, [%1];" : "=f"(x0) : "r"(xlane + (uint32_t)ib.x));
                asm volatile("ld.shared.f32 %0, [%1];" : "=f"(x1) : "r"(xlane + (uint32_t)ib.y));
                asm volatile("ld.shared.f32 %0, [%1];" : "=f"(x2) : "r"(xlane + (uint32_t)ib.z));
                asm volatile("ld.shared.f32 %0, [%1];" : "=f"(x3) : "r"(xlane + (uint32_t)ib.w));
                a = fmaf(x0, wv.x, a);
                a = fmaf(x1, wv.y, a);
                a = fmaf(x2, wv.z, a);
                a = fmaf(x3, wv.w, a);
            }
            acc[r] = a;
        }
    }

    // --- epilogue: smem transpose -> coalesced STG ---
    __syncthreads();
    float* tw = sm + warp * (32 * 33);
#pragma unroll
    for (int r = 0; r < 32; r++) tw[lane * 33 + r] = acc[r];   // bank = lane+r
    __syncwarp();
#pragma unroll
    for (int tt = 0; tt < 32; tt++) {
        float v = tw[tt * 33 + lane];                          // bank = tt+lane
        out[(size_t)(t0 + tt) * 2048 + myrow0 + lane] = v;
    }
}

// ---------------------------------------------------------------------------
extern "C" void kernel_launch(void* const* d_in, const int* in_sizes, int n_in,
                              void* d_out, int out_size)
{
    const float *x_a, *w_a, *m_a, *x_b, *w_b, *m_b, *x_c, *w_c, *m_c;
    if (n_in >= 9 && in_sizes[1] == 4194304) {
        // dict insertion order: x_a, w_a, m_a, x_b, w_b, m_b, x_c, w_c, m_c
        x_a = (const float*)d_in[0]; w_a = (const float*)d_in[1]; m_a = (const float*)d_in[2];
        x_b = (const float*)d_in[3]; w_b = (const float*)d_in[4]; m_b = (const float*)d_in[5];
        x_c = (const float*)d_in[6]; w_c = (const float*)d_in[7]; m_c = (const float*)d_in[8];
    } else {
        // reference signature order: x_a, x_b, x_c, w_a, w_b, w_c, m_a, m_b, m_c
        x_a = (const float*)d_in[0]; x_b = (const float*)d_in[1]; x_c = (const float*)d_in[2];
        w_a = (const float*)d_in[3]; w_b = (const float*)d_in[4]; w_c = (const float*)d_in[5];
        m_a = (const float*)d_in[6]; m_b = (const float*)d_in[7]; m_c = (const float*)d_in[8];
    }

    float* out = (float*)d_out;

    prep_kernel<<<NROWS / 8, 256>>>(w_a, m_a, w_b, m_b, w_c, m_c);

    dim3 grid(8192 / NTOK, 4);
    gather_kernel<<<grid, TPB>>>(x_a, x_b, x_c, out);
}